// round 4
// baseline (speedup 1.0000x reference)
#include <cuda_runtime.h>
#include <math.h>
#include <stdint.h>

#define HIDDEN 512
#define BATCH  8
#define HW     2304   // 48*48

typedef long long ll;

// ---------------- scratch (static device globals; no allocs allowed) ----------
// All fp32, pre-rounded to tf32 where consumed by MMA.
static __device__ float g_lxT[(size_t)BATCH * HW * HIDDEN];  // locx^T [B][n][c]
static __device__ float g_gxT[(size_t)BATCH * HW * HIDDEN];  // glox^T [B][n][c]
static __device__ float g_q  [(size_t)BATCH * HW * HIDDEN];  // q   [B][n][c]
static __device__ float g_k  [(size_t)BATCH * HW * HIDDEN];  // k   [B][m][c]
static __device__ float g_v  [(size_t)BATCH * HIDDEN * HW];  // v   [B][c][m]
static __device__ float g_ctx[(size_t)BATCH * HW * HIDDEN];  // ctx [B][n][c]
static __device__ float g_S  [(size_t)BATCH * HW * HW];      // scores / probs
static __device__ float g_wq [HIDDEN * HIDDEN];
static __device__ float g_wk [HIDDEN * HIDDEN];
static __device__ float g_wv [HIDDEN * HIDDEN];
static __device__ float g_wo [HIDDEN * HIDDEN];

// ---------------- tf32 helpers ------------------------------------------------
__device__ __forceinline__ float f2tf32f(float f) {
    unsigned u;
    asm("cvt.rna.tf32.f32 %0, %1;" : "=r"(u) : "f"(f));
    return __uint_as_float(u);
}

__device__ __forceinline__ void mma_tf32(float& c0, float& c1, float& c2, float& c3,
                                         unsigned a0, unsigned a1, unsigned a2, unsigned a3,
                                         unsigned b0, unsigned b1)
{
    asm volatile(
        "mma.sync.aligned.m16n8k8.row.col.f32.tf32.tf32.f32 "
        "{%0,%1,%2,%3}, {%4,%5,%6,%7}, {%8,%9}, {%0,%1,%2,%3};"
        : "+f"(c0), "+f"(c1), "+f"(c2), "+f"(c3)
        : "r"(a0), "r"(a1), "r"(a2), "r"(a3), "r"(b0), "r"(b1));
}

// ---------------- fragment-major batched tf32 GEMM ----------------------------
// D[m][n] = alpha * sum_k A[m][k] * B[n][k] (+ bias)
// A: M x K row-major (k contiguous), B: N x K row-major (k contiguous).
// M, N multiples of 128; K multiple of 16.
// Smem tiles are stored in MMA-fragment order so fragment loads are LDS.128/LDS.64.
// BIAS: 0 none, 1 bias[row], 2 bias[col].  ROUND: tf32-round outputs.
constexpr int ATILE = 8192;            // bytes: 128m x 16k fp32
constexpr int BTILE = 8192;            // bytes: 128n x 16k fp32
constexpr int BUFB  = ATILE + BTILE;   // 16 KB per stage

template<int BIAS, bool ROUND>
__global__ __launch_bounds__(256, 2)
void gemm_fm(const float* __restrict__ A, int lda, ll sA,
             const float* __restrict__ B, int ldb, ll sB,
             float* __restrict__ C, int ldc, ll sC,
             const float* __restrict__ bias, int K, float alpha)
{
    __shared__ char smem[2 * BUFB];

    const int bz = blockIdx.z;
    A += (ll)bz * sA;
    B += (ll)bz * sB;

    const int bm = blockIdx.y * 128;
    const int bn = blockIdx.x * 128;
    const int tid  = threadIdx.x;
    const int warp = tid >> 5;
    const int lane = tid & 31;
    const int lr = lane >> 2;          // 0..7
    const int lc = lane & 3;           // 0..3
    const int wm = warp & 1;           // warp row-half (64 rows)
    const int wn = warp >> 1;          // warp col-quarter (32 cols)

    float acc[4][4][4];
#pragma unroll
    for (int i = 0; i < 4; i++)
#pragma unroll
        for (int j = 0; j < 4; j++)
#pragma unroll
            for (int r = 0; r < 4; r++) acc[i][j][r] = 0.f;

    float4 ra[2], rb[2];               // staging (one k16 chunk: 2 float4 each)

    auto LDGc = [&](int k0) {
#pragma unroll
        for (int p = 0; p < 2; p++) {
            int fi = tid + p * 256;            // 0..511
            int ksel = fi >> 7;                // 0..3 -> k = ksel*4 + j
            int rl   = fi & 127;               // row within tile
            ra[p] = *(const float4*)&A[(size_t)(bm + rl) * lda + k0 + ksel * 4];
            rb[p] = *(const float4*)&B[(size_t)(bn + rl) * ldb + k0 + ksel * 4];
        }
    };

    // scatter staging regs into fragment-major layout of buffer `buf`
    auto STSc = [&](int buf) {
        char* Ab = smem + buf * BUFB;
        char* Bb = smem + buf * BUFB + ATILE;
#pragma unroll
        for (int p = 0; p < 2; p++) {
            int fi = tid + p * 256;
            int ksel = fi >> 7;
            int rl   = fi & 127;
            float va[4] = { ra[p].x, ra[p].y, ra[p].z, ra[p].w };
            float vb[4] = { rb[p].x, rb[p].y, rb[p].z, rb[p].w };
            // A decomposition of row rl
            int awm = rl >> 6, ati = (rl >> 4) & 3, arh = (rl >> 3) & 1, alr = rl & 7;
            // B decomposition of row rl
            int bwn = rl >> 5, btj = (rl >> 3) & 3, bnr = rl & 7;
#pragma unroll
            for (int j = 0; j < 4; j++) {
                int kk    = ksel * 4 + j;
                int ks    = kk >> 3;
                int khalf = (kk >> 2) & 1;
                int kc    = kk & 3;
                // ---- A: idx = blockA*128 + lane*4 + r (words) ----
                int alane  = alr * 4 + kc;
                int arr    = arh + 2 * khalf;
                int blockA = (ks * 2 + awm) * 4 + ati;
                int aw     = blockA * 128 + alane * 4 + arr;
                int abyte  = (aw << 2) ^ (((((aw >> 5) & 3) ^ (blockA & 7))) << 4);
                *(float*)(Ab + abyte) = va[j];
                // ---- B: idx = blockB*64 + lane*2 + r (words) ----
                int blane  = bnr * 4 + kc;
                int blockB = (ks * 4 + bwn) * 4 + btj;
                int bw     = blockB * 64 + blane * 2 + khalf;
                int bbyte  = (bw << 2) ^ ((blockB & 15) << 3);
                *(float*)(Bb + bbyte) = vb[j];
            }
        }
    };

    const int nT = K >> 4;
    LDGc(0);
    STSc(0);
    __syncthreads();

    for (int t = 0; t < nT; t++) {
        const int cur = t & 1;
        if (t + 1 < nT) LDGc((t + 1) << 4);

        const char* Ab = smem + cur * BUFB;
        const char* Bb = smem + cur * BUFB + ATILE;
#pragma unroll
        for (int ks = 0; ks < 2; ks++) {
            uint4 af[4];
            uint2 bf[4];
#pragma unroll
            for (int ti = 0; ti < 4; ti++) {
                int blockA = (ks * 2 + wm) * 4 + ti;
                int base   = blockA * 512 + lane * 16;
                int addr   = base ^ ((((lane >> 3) ^ (blockA & 7))) << 4);
                af[ti] = *(const uint4*)(Ab + addr);
            }
#pragma unroll
            for (int tj = 0; tj < 4; tj++) {
                int blockB = (ks * 4 + wn) * 4 + tj;
                int base   = blockB * 256 + lane * 8;
                int addr   = base ^ ((blockB & 15) << 3);
                bf[tj] = *(const uint2*)(Bb + addr);
            }
#pragma unroll
            for (int ti = 0; ti < 4; ti++)
#pragma unroll
                for (int tj = 0; tj < 4; tj++)
                    mma_tf32(acc[ti][tj][0], acc[ti][tj][1], acc[ti][tj][2], acc[ti][tj][3],
                             af[ti].x, af[ti].y, af[ti].z, af[ti].w,
                             bf[tj].x, bf[tj].y);
        }
        if (t + 1 < nT) {
            STSc(cur ^ 1);
            __syncthreads();
        }
    }

    // ---- epilogue ----
    C += (ll)bz * sC;
#pragma unroll
    for (int ti = 0; ti < 4; ti++) {
        int r0 = bm + wm * 64 + ti * 16 + lr;
        int r1 = r0 + 8;
        float bv0 = (BIAS == 1) ? bias[r0] : 0.f;
        float bv1 = (BIAS == 1) ? bias[r1] : 0.f;
#pragma unroll
        for (int tj = 0; tj < 4; tj++) {
            int col = bn + wn * 32 + tj * 8 + lc * 2;
            float c0 = alpha * acc[ti][tj][0];
            float c1 = alpha * acc[ti][tj][1];
            float c2 = alpha * acc[ti][tj][2];
            float c3 = alpha * acc[ti][tj][3];
            if (BIAS == 1) { c0 += bv0; c1 += bv0; c2 += bv1; c3 += bv1; }
            if (BIAS == 2) {
                float b0 = bias[col], b1 = bias[col + 1];
                c0 += b0; c1 += b1; c2 += b0; c3 += b1;
            }
            if (ROUND) {
                c0 = f2tf32f(c0); c1 = f2tf32f(c1);
                c2 = f2tf32f(c2); c3 = f2tf32f(c3);
            }
            float2 o0 = { c0, c1 };
            float2 o1 = { c2, c3 };
            *(float2*)&C[(size_t)r0 * ldc + col] = o0;
            *(float2*)&C[(size_t)r1 * ldc + col] = o1;
        }
    }
}

// ---------------- transpose + tf32-round: X[B][C][N] -> T[B][N][C] ------------
__global__ __launch_bounds__(256)
void tround_kernel(const float* __restrict__ X, float* __restrict__ T)
{
    __shared__ float tb[32][33];
    const int b = blockIdx.z;
    const float* x = X + (size_t)b * HIDDEN * HW;
    float* t = T + (size_t)b * HW * HIDDEN;
    const int n0 = blockIdx.x * 32, c0 = blockIdx.y * 32;
    const int tx = threadIdx.x & 31, ty = threadIdx.x >> 5;
#pragma unroll
    for (int j = 0; j < 4; j++)
        tb[ty + j * 8][tx] = x[(size_t)(c0 + ty + j * 8) * HW + n0 + tx];
    __syncthreads();
#pragma unroll
    for (int j = 0; j < 4; j++)
        t[(size_t)(n0 + ty + j * 8) * HIDDEN + c0 + tx] = f2tf32f(tb[tx][ty + j * 8]);
}

// ---------------- elementwise tf32 round --------------------------------------
__global__ void roundw_kernel(const float* __restrict__ W, float* __restrict__ R, int n)
{
    int i = blockIdx.x * 256 + threadIdx.x;
    if (i < n) R[i] = f2tf32f(W[i]);
}

// ---------------- in-place row softmax (len HW = 2304 = 9*256), tf32 out ------
__global__ __launch_bounds__(256)
void softmax_kernel(float* __restrict__ S)
{
    const size_t row = blockIdx.x;
    float* p = S + row * (size_t)HW;
    const int tid = threadIdx.x;

    float vals[9];
    float mx = -1e30f;
#pragma unroll
    for (int i = 0; i < 9; i++) { vals[i] = p[tid + i * 256]; mx = fmaxf(mx, vals[i]); }
#pragma unroll
    for (int o = 16; o > 0; o >>= 1) mx = fmaxf(mx, __shfl_xor_sync(0xFFFFFFFFu, mx, o));
    __shared__ float rm[8], rs[8];
    if ((tid & 31) == 0) rm[tid >> 5] = mx;
    __syncthreads();
    float m = rm[0];
#pragma unroll
    for (int i = 1; i < 8; i++) m = fmaxf(m, rm[i]);

    float s = 0.f;
#pragma unroll
    for (int i = 0; i < 9; i++) { vals[i] = __expf(vals[i] - m); s += vals[i]; }
#pragma unroll
    for (int o = 16; o > 0; o >>= 1) s += __shfl_xor_sync(0xFFFFFFFFu, s, o);
    if ((tid & 31) == 0) rs[tid >> 5] = s;
    __syncthreads();
    float tot = 0.f;
#pragma unroll
    for (int i = 0; i < 8; i++) tot += rs[i];
    float inv = 1.f / tot;
#pragma unroll
    for (int i = 0; i < 9; i++) p[tid + i * 256] = f2tf32f(vals[i] * inv);
}

// ---------------- launch -----------------------------------------------------
extern "C" void kernel_launch(void* const* d_in, const int* in_sizes, int n_in,
                              void* d_out, int out_size)
{
    const float* locx = (const float*)d_in[0];
    const float* glox = (const float*)d_in[1];
    const float* Wq = (const float*)d_in[2];  const float* bq = (const float*)d_in[3];
    const float* Wk = (const float*)d_in[4];  const float* bk = (const float*)d_in[5];
    const float* Wv = (const float*)d_in[6];  const float* bv = (const float*)d_in[7];
    const float* Wo = (const float*)d_in[8];  const float* bo = (const float*)d_in[9];
    float* out = (float*)d_out;

#define SYMF(p, s) void* p##_; cudaGetSymbolAddress(&p##_, s); float* p = (float*)p##_
    SYMF(lxT, g_lxT); SYMF(gxT, g_gxT);
    SYMF(q, g_q); SYMF(k, g_k); SYMF(v, g_v); SYMF(ctx, g_ctx); SYMF(S, g_S);
    SYMF(wq, g_wq); SYMF(wk, g_wk); SYMF(wv, g_wv); SYMF(wo, g_wo);
#undef SYMF

    const ll sX = (ll)HW * HIDDEN;   // [n][c] tensors per-batch stride
    const ll sV = (ll)HIDDEN * HW;   // [c][m] tensors per-batch stride
    const ll sS = (ll)HW * HW;
    const float SCALE = 0.044194173824159216f;   // 1/sqrt(512)
    const int NW = HIDDEN * HIDDEN;

    dim3 blk(256);
    dim3 gNC(HIDDEN / 128, HW / 128, BATCH);     // D rows = HW, cols = HIDDEN
    dim3 gCN(HW / 128, HIDDEN / 128, BATCH);     // D rows = HIDDEN, cols = HW
    dim3 gNN(HW / 128, HW / 128, BATCH);         // D rows = HW, cols = HW

    // 0) tf32-round weights + transpose-round inputs
    roundw_kernel<<<(NW + 255) / 256, 256>>>(Wq, wq, NW);
    roundw_kernel<<<(NW + 255) / 256, 256>>>(Wk, wk, NW);
    roundw_kernel<<<(NW + 255) / 256, 256>>>(Wv, wv, NW);
    roundw_kernel<<<(NW + 255) / 256, 256>>>(Wo, wo, NW);
    tround_kernel<<<dim3(HW / 32, HIDDEN / 32, BATCH), 256>>>(locx, lxT);
    tround_kernel<<<dim3(HW / 32, HIDDEN / 32, BATCH), 256>>>(glox, gxT);

    // 1) q[n,co] = lxT[n,:] . Wq[co,:] + bq[co]    (bias on cols, rounded)
    gemm_fm<2, true><<<gNC, blk>>>(lxT, HIDDEN, sX, wq, HIDDEN, 0,
                                   q, HIDDEN, sX, bq, HIDDEN, 1.f);
    // 2) k[m,co] = gxT[m,:] . Wk[co,:] + bk[co]
    gemm_fm<2, true><<<gNC, blk>>>(gxT, HIDDEN, sX, wk, HIDDEN, 0,
                                   k, HIDDEN, sX, bk, HIDDEN, 1.f);
    // 3) v[co,m] = Wv[co,:] . gxT[m,:] + bv[co]    (bias on rows, rounded)
    gemm_fm<1, true><<<gCN, blk>>>(wv, HIDDEN, 0, gxT, HIDDEN, sX,
                                   v, HW, sV, bv, HIDDEN, 1.f);
    // 4) S[n,m] = SCALE * q[n,:] . k[m,:]
    gemm_fm<0, false><<<gNN, blk>>>(q, HIDDEN, sX, k, HIDDEN, sX,
                                    S, HW, sS, nullptr, HIDDEN, SCALE);
    // 5) in-place softmax rows -> tf32 P
    softmax_kernel<<<BATCH * HW, 256>>>(S);
    // 6) ctx[n,co] = P[n,:] . v[co,:]              (rounded)
    gemm_fm<0, true><<<gNC, blk>>>(S, HW, sS, v, HW, sV,
                                   ctx, HIDDEN, sX, nullptr, HW, 1.f);
    // 7) out[co,n] = Wo[co,:] . ctx[n,:] + bo[co]  (fp32 out)
    gemm_fm<1, false><<<gCN, blk>>>(wo, HIDDEN, 0, ctx, HIDDEN, sX,
                                    out, HW, sV, bo, HIDDEN, 1.f);
}

// round 6
// speedup vs baseline: 1.7601x; 1.7601x over previous
#include <cuda_runtime.h>
#include <math.h>
#include <stdint.h>

#define HIDDEN 512
#define BATCH  8
#define HW     2304   // 48*48

typedef long long ll;

// ---------------- scratch (static device globals; no allocs allowed) ----------
// All fp32, pre-rounded to tf32 where consumed by MMA.
static __device__ float g_lxT[(size_t)BATCH * HW * HIDDEN];  // locx^T [B][n][c]
static __device__ float g_gxT[(size_t)BATCH * HW * HIDDEN];  // glox^T [B][n][c]
static __device__ float g_q  [(size_t)BATCH * HW * HIDDEN];  // q   [B][n][c]
static __device__ float g_k  [(size_t)BATCH * HW * HIDDEN];  // k   [B][m][c]
static __device__ float g_v  [(size_t)BATCH * HIDDEN * HW];  // v   [B][c][m]
static __device__ float g_ctx[(size_t)BATCH * HW * HIDDEN];  // ctx [B][n][c]
static __device__ float g_S  [(size_t)BATCH * HW * HW];      // scores / probs
static __device__ float g_wq [HIDDEN * HIDDEN];
static __device__ float g_wk [HIDDEN * HIDDEN];
static __device__ float g_wv [HIDDEN * HIDDEN];
static __device__ float g_wo [HIDDEN * HIDDEN];

// ---------------- helpers -----------------------------------------------------
__device__ __forceinline__ float f2tf32f(float f) {
    unsigned u;
    asm("cvt.rna.tf32.f32 %0, %1;" : "=r"(u) : "f"(f));
    return __uint_as_float(u);
}
__device__ __forceinline__ uint32_t smem_u32(const void* p) {
    uint32_t a;
    asm("{ .reg .u64 t; cvta.to.shared.u64 t, %1; cvt.u32.u64 %0, t; }" : "=r"(a) : "l"(p));
    return a;
}
__device__ __forceinline__ void cp16(uint32_t dst, const void* src) {
    asm volatile("cp.async.cg.shared.global [%0], [%1], 16;" :: "r"(dst), "l"(src));
}
__device__ __forceinline__ void ldsm4(uint32_t& r0, uint32_t& r1, uint32_t& r2, uint32_t& r3,
                                      uint32_t addr) {
    asm volatile("ldmatrix.sync.aligned.m8n8.x4.shared.b16 {%0,%1,%2,%3}, [%4];"
                 : "=r"(r0), "=r"(r1), "=r"(r2), "=r"(r3) : "r"(addr));
}
__device__ __forceinline__ void mma_tf32(float& c0, float& c1, float& c2, float& c3,
                                         unsigned a0, unsigned a1, unsigned a2, unsigned a3,
                                         unsigned b0, unsigned b1)
{
    asm volatile(
        "mma.sync.aligned.m16n8k8.row.col.f32.tf32.tf32.f32 "
        "{%0,%1,%2,%3}, {%4,%5,%6,%7}, {%8,%9}, {%0,%1,%2,%3};"
        : "+f"(c0), "+f"(c1), "+f"(c2), "+f"(c3)
        : "r"(a0), "r"(a1), "r"(a2), "r"(a3), "r"(b0), "r"(b1));
}

// ---------------- ldmatrix + cp.async batched tf32 GEMM -----------------------
// D[m][n] = alpha * sum_k A[m][k] * B[n][k] (+ bias)
// A: M x K row-major (k contiguous), B: N x K row-major (k contiguous), fp32
// pre-rounded to tf32. M, N multiples of 128; K multiple of 32.
// Smem tile: row r at byte r*128, 16B chunk c stored at chunk (c ^ (r & 7)).
// BIAS: 0 none, 1 bias[row], 2 bias[col].  ROUND: tf32-round outputs.
constexpr int TILE  = 128 * 128;       // 16 KB: 128 rows x 32 k fp32
constexpr int STAGE = 2 * TILE;        // A + B per stage (32 KB)
constexpr int SMEMB = 2 * STAGE;       // 64 KB

template<int BIAS, bool ROUND>
__global__ __launch_bounds__(256, 2)
void gemm_ld(const float* __restrict__ A, int lda, ll sA,
             const float* __restrict__ B, int ldb, ll sB,
             float* __restrict__ C, int ldc, ll sC,
             const float* __restrict__ bias, int K, float alpha)
{
    extern __shared__ __align__(1024) char smem[];
    const uint32_t sb = smem_u32(smem);

    const int bz = blockIdx.z;
    A += (ll)bz * sA;
    B += (ll)bz * sB;

    const int bm = blockIdx.y * 128;
    const int bn = blockIdx.x * 128;
    const int tid  = threadIdx.x;
    const int warp = tid >> 5;
    const int lane = tid & 31;
    const int lr = lane >> 2;            // 0..7
    const int lc = lane & 3;             // 0..3
    const int wm = (warp & 1) * 64;      // warp m-origin within tile
    const int wn = (warp >> 1) * 32;     // warp n-origin within tile

    // ---- cp.async source/dest (per-thread, loop-invariant) ----
    const int row  = tid >> 1;           // 0..127
    const int half = tid & 1;            // which 64B half of the 128B row
    const float* gA = A + (size_t)(bm + row) * lda + half * 16;
    const float* gB = B + (size_t)(bn + row) * ldb + half * 16;
    uint32_t dA[4], dB[4];
#pragma unroll
    for (int j = 0; j < 4; j++) {
        int c = half * 4 + j;
        uint32_t off = row * 128 + (((c ^ (row & 7))) << 4);
        dA[j] = sb + off;
        dB[j] = sb + TILE + off;
    }

    // ---- ldmatrix lane-address components ----
    const int mi = lane >> 3;            // matrix id 0..3
    const int li = lane & 7;             // row-within-matrix
    // A: mi&1 -> +8 rows, mi>>1 -> +1 chunk
    const uint32_t aoff = (uint32_t)(wm + (mi & 1) * 8 + li) * 128;
    const int     achk = mi >> 1;
    // B: mi>>1 -> +8 rows (tj within pair), mi&1 -> +1 chunk
    const uint32_t boff = TILE + (uint32_t)(wn + (mi >> 1) * 8 + li) * 128;
    const int     bchk = mi & 1;

    float acc[4][4][4];
#pragma unroll
    for (int i = 0; i < 4; i++)
#pragma unroll
        for (int j = 0; j < 4; j++)
#pragma unroll
            for (int r = 0; r < 4; r++) acc[i][j][r] = 0.f;

    auto ISSUE = [&](int s, int k0) {
        uint32_t st = s * STAGE;
#pragma unroll
        for (int j = 0; j < 4; j++) cp16(dA[j] + st, gA + k0 + j * 4);
#pragma unroll
        for (int j = 0; j < 4; j++) cp16(dB[j] + st, gB + k0 + j * 4);
        asm volatile("cp.async.commit_group;");
    };

    const int nT = K >> 5;
    ISSUE(0, 0);

    for (int t = 0; t < nT; t++) {
        const int cur = t & 1;
        if (t + 1 < nT) {
            ISSUE(cur ^ 1, (t + 1) << 5);
            asm volatile("cp.async.wait_group 1;");
        } else {
            asm volatile("cp.async.wait_group 0;");
        }
        __syncthreads();

        const uint32_t st = sb + cur * STAGE;
#pragma unroll
        for (int ks = 0; ks < 4; ks++) {
            const int c0 = ks * 2;
            uint32_t af[4][4];
            uint32_t bf[4][2];
#pragma unroll
            for (int ti = 0; ti < 4; ti++)
                ldsm4(af[ti][0], af[ti][1], af[ti][2], af[ti][3],
                      st + ti * 2048 + aoff + (((c0 + achk) ^ li) << 4));
#pragma unroll
            for (int tp = 0; tp < 2; tp++)
                ldsm4(bf[2 * tp][0], bf[2 * tp][1], bf[2 * tp + 1][0], bf[2 * tp + 1][1],
                      st + tp * 2048 + boff + (((c0 + bchk) ^ li) << 4));
#pragma unroll
            for (int ti = 0; ti < 4; ti++)
#pragma unroll
                for (int tj = 0; tj < 4; tj++)
                    mma_tf32(acc[ti][tj][0], acc[ti][tj][1], acc[ti][tj][2], acc[ti][tj][3],
                             af[ti][0], af[ti][1], af[ti][2], af[ti][3],
                             bf[tj][0], bf[tj][1]);
        }
        __syncthreads();
    }

    // ---- epilogue ----
    C += (ll)bz * sC;
#pragma unroll
    for (int ti = 0; ti < 4; ti++) {
        int r0 = bm + wm + ti * 16 + lr;
        int r1 = r0 + 8;
        float bv0 = (BIAS == 1) ? bias[r0] : 0.f;
        float bv1 = (BIAS == 1) ? bias[r1] : 0.f;
#pragma unroll
        for (int tj = 0; tj < 4; tj++) {
            int col = bn + wn + tj * 8 + lc * 2;
            float c0 = alpha * acc[ti][tj][0];
            float c1 = alpha * acc[ti][tj][1];
            float c2 = alpha * acc[ti][tj][2];
            float c3 = alpha * acc[ti][tj][3];
            if (BIAS == 1) { c0 += bv0; c1 += bv0; c2 += bv1; c3 += bv1; }
            if (BIAS == 2) {
                float b0 = bias[col], b1 = bias[col + 1];
                c0 += b0; c1 += b1; c2 += b0; c3 += b1;
            }
            if (ROUND) {
                c0 = f2tf32f(c0); c1 = f2tf32f(c1);
                c2 = f2tf32f(c2); c3 = f2tf32f(c3);
            }
            float2 o0 = { c0, c1 };
            float2 o1 = { c2, c3 };
            *(float2*)&C[(size_t)r0 * ldc + col] = o0;
            *(float2*)&C[(size_t)r1 * ldc + col] = o1;
        }
    }
}

// ---------------- transpose + tf32-round: X[B][C][N] -> T[B][N][C] ------------
__global__ __launch_bounds__(256)
void tround_kernel(const float* __restrict__ X, float* __restrict__ T)
{
    __shared__ float tb[32][33];
    const int b = blockIdx.z;
    const float* x = X + (size_t)b * HIDDEN * HW;
    float* t = T + (size_t)b * HW * HIDDEN;
    const int n0 = blockIdx.x * 32, c0 = blockIdx.y * 32;
    const int tx = threadIdx.x & 31, ty = threadIdx.x >> 5;
#pragma unroll
    for (int j = 0; j < 4; j++)
        tb[ty + j * 8][tx] = x[(size_t)(c0 + ty + j * 8) * HW + n0 + tx];
    __syncthreads();
#pragma unroll
    for (int j = 0; j < 4; j++)
        t[(size_t)(n0 + ty + j * 8) * HIDDEN + c0 + tx] = f2tf32f(tb[tx][ty + j * 8]);
}

// ---------------- elementwise tf32 round --------------------------------------
__global__ void roundw_kernel(const float* __restrict__ W, float* __restrict__ R, int n)
{
    int i = blockIdx.x * 256 + threadIdx.x;
    if (i < n) R[i] = f2tf32f(W[i]);
}

// ---------------- in-place row softmax (len HW = 2304 = 9*256), tf32 out ------
__global__ __launch_bounds__(256)
void softmax_kernel(float* __restrict__ S)
{
    const size_t row = blockIdx.x;
    float* p = S + row * (size_t)HW;
    const int tid = threadIdx.x;

    float vals[9];
    float mx = -1e30f;
#pragma unroll
    for (int i = 0; i < 9; i++) { vals[i] = p[tid + i * 256]; mx = fmaxf(mx, vals[i]); }
#pragma unroll
    for (int o = 16; o > 0; o >>= 1) mx = fmaxf(mx, __shfl_xor_sync(0xFFFFFFFFu, mx, o));
    __shared__ float rm[8], rs[8];
    if ((tid & 31) == 0) rm[tid >> 5] = mx;
    __syncthreads();
    float m = rm[0];
#pragma unroll
    for (int i = 1; i < 8; i++) m = fmaxf(m, rm[i]);

    float s = 0.f;
#pragma unroll
    for (int i = 0; i < 9; i++) { vals[i] = __expf(vals[i] - m); s += vals[i]; }
#pragma unroll
    for (int o = 16; o > 0; o >>= 1) s += __shfl_xor_sync(0xFFFFFFFFu, s, o);
    if ((tid & 31) == 0) rs[tid >> 5] = s;
    __syncthreads();
    float tot = 0.f;
#pragma unroll
    for (int i = 0; i < 8; i++) tot += rs[i];
    float inv = 1.f / tot;
#pragma unroll
    for (int i = 0; i < 9; i++) p[tid + i * 256] = f2tf32f(vals[i] * inv);
}

// ---------------- launch -----------------------------------------------------
extern "C" void kernel_launch(void* const* d_in, const int* in_sizes, int n_in,
                              void* d_out, int out_size)
{
    const float* locx = (const float*)d_in[0];
    const float* glox = (const float*)d_in[1];
    const float* Wq = (const float*)d_in[2];  const float* bq = (const float*)d_in[3];
    const float* Wk = (const float*)d_in[4];  const float* bk = (const float*)d_in[5];
    const float* Wv = (const float*)d_in[6];  const float* bv = (const float*)d_in[7];
    const float* Wo = (const float*)d_in[8];  const float* bo = (const float*)d_in[9];
    float* out = (float*)d_out;

#define SYMF(p, s) void* p##_; cudaGetSymbolAddress(&p##_, s); float* p = (float*)p##_
    SYMF(lxT, g_lxT); SYMF(gxT, g_gxT);
    SYMF(q, g_q); SYMF(k, g_k); SYMF(v, g_v); SYMF(ctx, g_ctx); SYMF(S, g_S);
    SYMF(wq, g_wq); SYMF(wk, g_wk); SYMF(wv, g_wv); SYMF(wo, g_wo);
#undef SYMF

    cudaFuncSetAttribute(gemm_ld<0, false>, cudaFuncAttributeMaxDynamicSharedMemorySize, SMEMB);
    cudaFuncSetAttribute(gemm_ld<0, true>,  cudaFuncAttributeMaxDynamicSharedMemorySize, SMEMB);
    cudaFuncSetAttribute(gemm_ld<1, false>, cudaFuncAttributeMaxDynamicSharedMemorySize, SMEMB);
    cudaFuncSetAttribute(gemm_ld<1, true>,  cudaFuncAttributeMaxDynamicSharedMemorySize, SMEMB);
    cudaFuncSetAttribute(gemm_ld<2, true>,  cudaFuncAttributeMaxDynamicSharedMemorySize, SMEMB);

    const ll sX = (ll)HW * HIDDEN;   // [n][c] tensors per-batch stride
    const ll sV = (ll)HIDDEN * HW;   // [c][m] tensors per-batch stride
    const ll sS = (ll)HW * HW;
    const float SCALE = 0.044194173824159216f;   // 1/sqrt(512)
    const int NW = HIDDEN * HIDDEN;

    dim3 blk(256);
    dim3 gNC(HIDDEN / 128, HW / 128, BATCH);     // D rows = HW, cols = HIDDEN
    dim3 gCN(HW / 128, HIDDEN / 128, BATCH);     // D rows = HIDDEN, cols = HW
    dim3 gNN(HW / 128, HW / 128, BATCH);         // D rows = HW, cols = HW

    // 0) tf32-round weights + transpose-round inputs
    roundw_kernel<<<(NW + 255) / 256, 256>>>(Wq, wq, NW);
    roundw_kernel<<<(NW + 255) / 256, 256>>>(Wk, wk, NW);
    roundw_kernel<<<(NW + 255) / 256, 256>>>(Wv, wv, NW);
    roundw_kernel<<<(NW + 255) / 256, 256>>>(Wo, wo, NW);
    tround_kernel<<<dim3(HW / 32, HIDDEN / 32, BATCH), 256>>>(locx, lxT);
    tround_kernel<<<dim3(HW / 32, HIDDEN / 32, BATCH), 256>>>(glox, gxT);

    // 1) q[n,co] = lxT[n,:] . Wq[co,:] + bq[co]    (bias on cols, rounded)
    gemm_ld<2, true><<<gNC, blk, SMEMB>>>(lxT, HIDDEN, sX, wq, HIDDEN, 0,
                                          q, HIDDEN, sX, bq, HIDDEN, 1.f);
    // 2) k[m,co] = gxT[m,:] . Wk[co,:] + bk[co]
    gemm_ld<2, true><<<gNC, blk, SMEMB>>>(gxT, HIDDEN, sX, wk, HIDDEN, 0,
                                          k, HIDDEN, sX, bk, HIDDEN, 1.f);
    // 3) v[co,m] = Wv[co,:] . gxT[m,:] + bv[co]    (bias on rows, rounded)
    gemm_ld<1, true><<<gCN, blk, SMEMB>>>(wv, HIDDEN, 0, gxT, HIDDEN, sX,
                                          v, HW, sV, bv, HIDDEN, 1.f);
    // 4) S[n,m] = SCALE * q[n,:] . k[m,:]
    gemm_ld<0, false><<<gNN, blk, SMEMB>>>(q, HIDDEN, sX, k, HIDDEN, sX,
                                           S, HW, sS, nullptr, HIDDEN, SCALE);
    // 5) in-place softmax rows -> tf32 P
    softmax_kernel<<<BATCH * HW, 256>>>(S);
    // 6) ctx[n,co] = P[n,:] . v[co,:]              (rounded)
    gemm_ld<0, true><<<gNC, blk, SMEMB>>>(S, HW, sS, v, HW, sV,
                                          ctx, HIDDEN, sX, nullptr, HW, 1.f);
    // 7) out[co,n] = Wo[co,:] . ctx[n,:] + bo[co]  (fp32 out)
    gemm_ld<1, false><<<gCN, blk, SMEMB>>>(wo, HIDDEN, 0, ctx, HIDDEN, sX,
                                           out, HW, sV, bo, HIDDEN, 1.f);
}

// round 7
// speedup vs baseline: 1.8205x; 1.0343x over previous
#include <cuda_runtime.h>
#include <math.h>
#include <stdint.h>

#define HIDDEN 512
#define BATCH  8
#define HW     2304   // 48*48

typedef long long ll;

// ---------------- scratch (static device globals; no allocs allowed) ----------
// All fp32, pre-rounded to tf32 where consumed by MMA.
static __device__ float g_lxT[(size_t)BATCH * HW * HIDDEN];  // locx^T [B][n][c]
static __device__ float g_gxT[(size_t)BATCH * HW * HIDDEN];  // glox^T [B][n][c]
static __device__ float g_q  [(size_t)BATCH * HW * HIDDEN];  // q   [B][n][c]
static __device__ float g_k  [(size_t)BATCH * HW * HIDDEN];  // k   [B][m][c]
static __device__ float g_v  [(size_t)BATCH * HIDDEN * HW];  // v   [B][c][m]
static __device__ float g_ctx[(size_t)BATCH * HW * HIDDEN];  // ctx [B][n][c]
static __device__ float g_S  [(size_t)BATCH * HW * HW];      // scores / probs
static __device__ float g_wq [HIDDEN * HIDDEN];
static __device__ float g_wk [HIDDEN * HIDDEN];
static __device__ float g_wv [HIDDEN * HIDDEN];
static __device__ float g_wo [HIDDEN * HIDDEN];

// ---------------- helpers -----------------------------------------------------
__device__ __forceinline__ float f2tf32f(float f) {
    unsigned u;
    asm("cvt.rna.tf32.f32 %0, %1;" : "=r"(u) : "f"(f));
    return __uint_as_float(u);
}
__device__ __forceinline__ uint32_t smem_u32(const void* p) {
    uint32_t a;
    asm("{ .reg .u64 t; cvta.to.shared.u64 t, %1; cvt.u32.u64 %0, t; }" : "=r"(a) : "l"(p));
    return a;
}
__device__ __forceinline__ void cp16(uint32_t dst, const void* src) {
    asm volatile("cp.async.cg.shared.global [%0], [%1], 16;" :: "r"(dst), "l"(src));
}
__device__ __forceinline__ void ldsm4(uint32_t& r0, uint32_t& r1, uint32_t& r2, uint32_t& r3,
                                      uint32_t addr) {
    asm volatile("ldmatrix.sync.aligned.m8n8.x4.shared.b16 {%0,%1,%2,%3}, [%4];"
                 : "=r"(r0), "=r"(r1), "=r"(r2), "=r"(r3) : "r"(addr));
}
__device__ __forceinline__ void mma_tf32(float& c0, float& c1, float& c2, float& c3,
                                         unsigned a0, unsigned a1, unsigned a2, unsigned a3,
                                         unsigned b0, unsigned b1)
{
    asm volatile(
        "mma.sync.aligned.m16n8k8.row.col.f32.tf32.tf32.f32 "
        "{%0,%1,%2,%3}, {%4,%5,%6,%7}, {%8,%9}, {%0,%1,%2,%3};"
        : "+f"(c0), "+f"(c1), "+f"(c2), "+f"(c3)
        : "r"(a0), "r"(a1), "r"(a2), "r"(a3), "r"(b0), "r"(b1));
}

// ---------------- ldmatrix + cp.async batched tf32 GEMM (3-stage) -------------
// D[m][n] = alpha * sum_k A[m][k] * B[n][k] (+ bias)
// A: M x K row-major (k contiguous), B: N x K row-major (k contiguous), fp32
// pre-rounded to tf32. M, N multiples of 128; K multiple of 32 (and >= 64).
// Smem tile: row r at byte r*128, 16B chunk c stored at chunk (c ^ (r & 7)).
// BIAS: 0 none, 1 bias[row], 2 bias[col].  ROUND: tf32-round outputs.
constexpr int TILE   = 128 * 128;       // 16 KB: 128 rows x 32 k fp32
constexpr int STAGE  = 2 * TILE;        // A + B per stage (32 KB)
constexpr int NSTAGE = 3;
constexpr int SMEMB  = NSTAGE * STAGE;  // 96 KB

template<int BIAS, bool ROUND>
__global__ __launch_bounds__(256, 2)
void gemm_ld(const float* __restrict__ A, int lda, ll sA,
             const float* __restrict__ B, int ldb, ll sB,
             float* __restrict__ C, int ldc, ll sC,
             const float* __restrict__ bias, int K, float alpha)
{
    extern __shared__ __align__(1024) char smem[];
    const uint32_t sb = smem_u32(smem);

    const int bz = blockIdx.z;
    A += (ll)bz * sA;
    B += (ll)bz * sB;

    const int bm = blockIdx.y * 128;
    const int bn = blockIdx.x * 128;
    const int tid  = threadIdx.x;
    const int warp = tid >> 5;
    const int lane = tid & 31;
    const int lr = lane >> 2;            // 0..7
    const int lc = lane & 3;             // 0..3
    const int wm = (warp & 1) * 64;      // warp m-origin within tile
    const int wn = (warp >> 1) * 32;     // warp n-origin within tile

    // ---- cp.async source/dest (per-thread, loop-invariant) ----
    const int row  = tid >> 1;           // 0..127
    const int half = tid & 1;            // which 64B half of the 128B row
    const float* gA = A + (size_t)(bm + row) * lda + half * 16;
    const float* gB = B + (size_t)(bn + row) * ldb + half * 16;
    uint32_t dA[4], dB[4];
#pragma unroll
    for (int j = 0; j < 4; j++) {
        int c = half * 4 + j;
        uint32_t off = row * 128 + (((c ^ (row & 7))) << 4);
        dA[j] = sb + off;
        dB[j] = sb + TILE + off;
    }

    // ---- ldmatrix lane-address components ----
    const int mi = lane >> 3;            // matrix id 0..3
    const int li = lane & 7;             // row-within-matrix
    const uint32_t aoff = (uint32_t)(wm + (mi & 1) * 8 + li) * 128;
    const int     achk = mi >> 1;
    const uint32_t boff = TILE + (uint32_t)(wn + (mi >> 1) * 8 + li) * 128;
    const int     bchk = mi & 1;

    float acc[4][4][4];
#pragma unroll
    for (int i = 0; i < 4; i++)
#pragma unroll
        for (int j = 0; j < 4; j++)
#pragma unroll
            for (int r = 0; r < 4; r++) acc[i][j][r] = 0.f;

    auto ISSUE = [&](int s, int k0) {
        uint32_t st = s * STAGE;
#pragma unroll
        for (int j = 0; j < 4; j++) cp16(dA[j] + st, gA + k0 + j * 4);
#pragma unroll
        for (int j = 0; j < 4; j++) cp16(dB[j] + st, gB + k0 + j * 4);
        asm volatile("cp.async.commit_group;");
    };

    const int nT = K >> 5;               // >= 2 for every call here
    ISSUE(0, 0);
    ISSUE(1, 32);

    int stage = 0;
    for (int t = 0; t < nT; t++) {
        if (t < nT - 1) asm volatile("cp.async.wait_group 1;");
        else            asm volatile("cp.async.wait_group 0;");
        __syncthreads();

        if (t + 2 < nT) {
            int ps = stage + 2; if (ps >= NSTAGE) ps -= NSTAGE;
            ISSUE(ps, (t + 2) << 5);
        }

        const uint32_t st = sb + stage * STAGE;
#pragma unroll
        for (int ks = 0; ks < 4; ks++) {
            const int c0 = ks * 2;
            uint32_t af[4][4];
            uint32_t bf[4][2];
#pragma unroll
            for (int ti = 0; ti < 4; ti++)
                ldsm4(af[ti][0], af[ti][1], af[ti][2], af[ti][3],
                      st + ti * 2048 + aoff + (((c0 + achk) ^ li) << 4));
#pragma unroll
            for (int tp = 0; tp < 2; tp++)
                ldsm4(bf[2 * tp][0], bf[2 * tp][1], bf[2 * tp + 1][0], bf[2 * tp + 1][1],
                      st + tp * 2048 + boff + (((c0 + bchk) ^ li) << 4));
#pragma unroll
            for (int ti = 0; ti < 4; ti++)
#pragma unroll
                for (int tj = 0; tj < 4; tj++)
                    mma_tf32(acc[ti][tj][0], acc[ti][tj][1], acc[ti][tj][2], acc[ti][tj][3],
                             af[ti][0], af[ti][1], af[ti][2], af[ti][3],
                             bf[tj][0], bf[tj][1]);
        }
        if (++stage == NSTAGE) stage = 0;
    }

    // ---- epilogue ----
    C += (ll)bz * sC;
#pragma unroll
    for (int ti = 0; ti < 4; ti++) {
        int r0 = bm + wm + ti * 16 + lr;
        int r1 = r0 + 8;
        float bv0 = (BIAS == 1) ? bias[r0] : 0.f;
        float bv1 = (BIAS == 1) ? bias[r1] : 0.f;
#pragma unroll
        for (int tj = 0; tj < 4; tj++) {
            int col = bn + wn + tj * 8 + lc * 2;
            float c0 = alpha * acc[ti][tj][0];
            float c1 = alpha * acc[ti][tj][1];
            float c2 = alpha * acc[ti][tj][2];
            float c3 = alpha * acc[ti][tj][3];
            if (BIAS == 1) { c0 += bv0; c1 += bv0; c2 += bv1; c3 += bv1; }
            if (BIAS == 2) {
                float b0 = bias[col], b1 = bias[col + 1];
                c0 += b0; c1 += b1; c2 += b0; c3 += b1;
            }
            if (ROUND) {
                c0 = f2tf32f(c0); c1 = f2tf32f(c1);
                c2 = f2tf32f(c2); c3 = f2tf32f(c3);
            }
            float2 o0 = { c0, c1 };
            float2 o1 = { c2, c3 };
            *(float2*)&C[(size_t)r0 * ldc + col] = o0;
            *(float2*)&C[(size_t)r1 * ldc + col] = o1;
        }
    }
}

// ---------------- transpose + tf32-round: X[B][C][N] -> T[B][N][C] ------------
__global__ __launch_bounds__(256)
void tround_kernel(const float* __restrict__ X, float* __restrict__ T)
{
    __shared__ float tb[32][33];
    const int b = blockIdx.z;
    const float* x = X + (size_t)b * HIDDEN * HW;
    float* t = T + (size_t)b * HW * HIDDEN;
    const int n0 = blockIdx.x * 32, c0 = blockIdx.y * 32;
    const int tx = threadIdx.x & 31, ty = threadIdx.x >> 5;
#pragma unroll
    for (int j = 0; j < 4; j++)
        tb[ty + j * 8][tx] = x[(size_t)(c0 + ty + j * 8) * HW + n0 + tx];
    __syncthreads();
#pragma unroll
    for (int j = 0; j < 4; j++)
        t[(size_t)(n0 + ty + j * 8) * HIDDEN + c0 + tx] = f2tf32f(tb[tx][ty + j * 8]);
}

// ---------------- elementwise tf32 round --------------------------------------
__global__ void roundw_kernel(const float* __restrict__ W, float* __restrict__ R, int n)
{
    int i = blockIdx.x * 256 + threadIdx.x;
    if (i < n) R[i] = f2tf32f(W[i]);
}

// ---------------- in-place row softmax, vectorized (2304 = 288*2 float4) ------
__global__ __launch_bounds__(288)
void softmax_kernel(float* __restrict__ S)
{
    const size_t row = blockIdx.x;
    float4* p = (float4*)(S + row * (size_t)HW);
    const int tid = threadIdx.x;

    float4 va = p[tid];
    float4 vb = p[tid + 288];
    float mx = fmaxf(fmaxf(fmaxf(va.x, va.y), fmaxf(va.z, va.w)),
                     fmaxf(fmaxf(vb.x, vb.y), fmaxf(vb.z, vb.w)));
#pragma unroll
    for (int o = 16; o > 0; o >>= 1) mx = fmaxf(mx, __shfl_xor_sync(0xFFFFFFFFu, mx, o));
    __shared__ float rm[9], rs[9];
    if ((tid & 31) == 0) rm[tid >> 5] = mx;
    __syncthreads();
    float m = rm[0];
#pragma unroll
    for (int i = 1; i < 9; i++) m = fmaxf(m, rm[i]);

    va.x = __expf(va.x - m); va.y = __expf(va.y - m);
    va.z = __expf(va.z - m); va.w = __expf(va.w - m);
    vb.x = __expf(vb.x - m); vb.y = __expf(vb.y - m);
    vb.z = __expf(vb.z - m); vb.w = __expf(vb.w - m);
    float s = (va.x + va.y) + (va.z + va.w) + (vb.x + vb.y) + (vb.z + vb.w);
#pragma unroll
    for (int o = 16; o > 0; o >>= 1) s += __shfl_xor_sync(0xFFFFFFFFu, s, o);
    if ((tid & 31) == 0) rs[tid >> 5] = s;
    __syncthreads();
    float tot = 0.f;
#pragma unroll
    for (int i = 0; i < 9; i++) tot += rs[i];
    float inv = 1.f / tot;

    va.x = f2tf32f(va.x * inv); va.y = f2tf32f(va.y * inv);
    va.z = f2tf32f(va.z * inv); va.w = f2tf32f(va.w * inv);
    vb.x = f2tf32f(vb.x * inv); vb.y = f2tf32f(vb.y * inv);
    vb.z = f2tf32f(vb.z * inv); vb.w = f2tf32f(vb.w * inv);
    p[tid] = va;
    p[tid + 288] = vb;
}

// ---------------- launch -----------------------------------------------------
extern "C" void kernel_launch(void* const* d_in, const int* in_sizes, int n_in,
                              void* d_out, int out_size)
{
    const float* locx = (const float*)d_in[0];
    const float* glox = (const float*)d_in[1];
    const float* Wq = (const float*)d_in[2];  const float* bq = (const float*)d_in[3];
    const float* Wk = (const float*)d_in[4];  const float* bk = (const float*)d_in[5];
    const float* Wv = (const float*)d_in[6];  const float* bv = (const float*)d_in[7];
    const float* Wo = (const float*)d_in[8];  const float* bo = (const float*)d_in[9];
    float* out = (float*)d_out;

#define SYMF(p, s) void* p##_; cudaGetSymbolAddress(&p##_, s); float* p = (float*)p##_
    SYMF(lxT, g_lxT); SYMF(gxT, g_gxT);
    SYMF(q, g_q); SYMF(k, g_k); SYMF(v, g_v); SYMF(ctx, g_ctx); SYMF(S, g_S);
    SYMF(wq, g_wq); SYMF(wk, g_wk); SYMF(wv, g_wv); SYMF(wo, g_wo);
#undef SYMF

    cudaFuncSetAttribute(gemm_ld<0, false>, cudaFuncAttributeMaxDynamicSharedMemorySize, SMEMB);
    cudaFuncSetAttribute(gemm_ld<0, true>,  cudaFuncAttributeMaxDynamicSharedMemorySize, SMEMB);
    cudaFuncSetAttribute(gemm_ld<1, false>, cudaFuncAttributeMaxDynamicSharedMemorySize, SMEMB);
    cudaFuncSetAttribute(gemm_ld<1, true>,  cudaFuncAttributeMaxDynamicSharedMemorySize, SMEMB);
    cudaFuncSetAttribute(gemm_ld<2, true>,  cudaFuncAttributeMaxDynamicSharedMemorySize, SMEMB);

    const ll sX = (ll)HW * HIDDEN;   // [n][c] tensors per-batch stride
    const ll sV = (ll)HIDDEN * HW;   // [c][m] tensors per-batch stride
    const ll sS = (ll)HW * HW;
    const float SCALE = 0.044194173824159216f;   // 1/sqrt(512)
    const int NW = HIDDEN * HIDDEN;

    dim3 blk(256);
    dim3 gNC(HIDDEN / 128, HW / 128, BATCH);     // D rows = HW, cols = HIDDEN
    dim3 gCN(HW / 128, HIDDEN / 128, BATCH);     // D rows = HIDDEN, cols = HW
    dim3 gNN(HW / 128, HW / 128, BATCH);         // D rows = HW, cols = HW

    // 0) tf32-round weights + transpose-round inputs
    roundw_kernel<<<(NW + 255) / 256, 256>>>(Wq, wq, NW);
    roundw_kernel<<<(NW + 255) / 256, 256>>>(Wk, wk, NW);
    roundw_kernel<<<(NW + 255) / 256, 256>>>(Wv, wv, NW);
    roundw_kernel<<<(NW + 255) / 256, 256>>>(Wo, wo, NW);
    tround_kernel<<<dim3(HW / 32, HIDDEN / 32, BATCH), 256>>>(locx, lxT);
    tround_kernel<<<dim3(HW / 32, HIDDEN / 32, BATCH), 256>>>(glox, gxT);

    // 1) q[n,co] = lxT[n,:] . Wq[co,:] + bq[co]    (bias on cols, rounded)
    gemm_ld<2, true><<<gNC, blk, SMEMB>>>(lxT, HIDDEN, sX, wq, HIDDEN, 0,
                                          q, HIDDEN, sX, bq, HIDDEN, 1.f);
    // 2) k[m,co] = gxT[m,:] . Wk[co,:] + bk[co]
    gemm_ld<2, true><<<gNC, blk, SMEMB>>>(gxT, HIDDEN, sX, wk, HIDDEN, 0,
                                          k, HIDDEN, sX, bk, HIDDEN, 1.f);
    // 3) v[co,m] = Wv[co,:] . gxT[m,:] + bv[co]    (bias on rows, rounded)
    gemm_ld<1, true><<<gCN, blk, SMEMB>>>(wv, HIDDEN, 0, gxT, HIDDEN, sX,
                                          v, HW, sV, bv, HIDDEN, 1.f);
    // 4) S[n,m] = SCALE * q[n,:] . k[m,:]
    gemm_ld<0, false><<<gNN, blk, SMEMB>>>(q, HIDDEN, sX, k, HIDDEN, sX,
                                           S, HW, sS, nullptr, HIDDEN, SCALE);
    // 5) in-place softmax rows -> tf32 P
    softmax_kernel<<<BATCH * HW, 288>>>(S);
    // 6) ctx[n,co] = P[n,:] . v[co,:]              (rounded)
    gemm_ld<0, true><<<gNC, blk, SMEMB>>>(S, HW, sS, v, HW, sV,
                                          ctx, HIDDEN, sX, nullptr, HW, 1.f);
    // 7) out[co,n] = Wo[co,:] . ctx[n,:] + bo[co]  (fp32 out)
    gemm_ld<1, false><<<gCN, blk, SMEMB>>>(wo, HIDDEN, 0, ctx, HIDDEN, sX,
                                           out, HW, sV, bo, HIDDEN, 1.f);
}